// round 1
// baseline (speedup 1.0000x reference)
#include <cuda_runtime.h>
#include <cuda_bf16.h>
#include <math.h>

// ---------------- problem constants ----------------
#define BATCH   2
#define SEQ     2048
#define HIDDEN  4096
#define NH      32
#define NKV     4
#define QKD     192
#define VDIM    128
#define MROWS   (BATCH*SEQ)          // 4096
#define QCOLS   (NH*QKD)             // 6144
#define KCOLS   (NKV*QKD)            // 768
#define VCOLS   (NKV*VDIM)           // 512
#define OCOLS   (NH*VDIM)            // 4096

// ---------------- scratch (device globals: allocation-free) ----------------
__device__ float g_q[(size_t)MROWS * QCOLS];    // ~100 MB
__device__ float g_k[(size_t)MROWS * KCOLS];    // ~12.6 MB
__device__ float g_v[(size_t)MROWS * VCOLS];    // ~8.4 MB
__device__ float g_att[(size_t)MROWS * OCOLS];  // ~67 MB

// ---------------- SGEMM: C[M,N] = A[M,K] * B[N,K]^T  (all row-major) ------
// BM=BN=128, BK=8, 256 threads, 8x8 per thread.
__global__ __launch_bounds__(256)
void sgemm_tn(const float* __restrict__ A, const float* __restrict__ B,
              float* __restrict__ C, int M, int N, int K)
{
    const int BM = 128, BN = 128, BK = 8, TM = 8, TN = 8;
    __shared__ float As[BK][BM];
    __shared__ float Bs[BK][BN];

    int tid = threadIdx.x;
    int tr  = tid / (BN / TN);   // 0..15
    int tc  = tid % (BN / TN);   // 0..15
    int blockRow = blockIdx.y * BM;
    int blockCol = blockIdx.x * BN;

    int aRow = tid >> 1;              // 0..127
    int aCol = (tid & 1) * 4;         // 0 or 4

    float acc[TM][TN];
#pragma unroll
    for (int i = 0; i < TM; i++)
#pragma unroll
        for (int j = 0; j < TN; j++) acc[i][j] = 0.f;

    for (int k0 = 0; k0 < K; k0 += BK) {
        float4 a4 = *(const float4*)(A + (size_t)(blockRow + aRow) * K + k0 + aCol);
        As[aCol + 0][aRow] = a4.x;
        As[aCol + 1][aRow] = a4.y;
        As[aCol + 2][aRow] = a4.z;
        As[aCol + 3][aRow] = a4.w;
        float4 b4 = *(const float4*)(B + (size_t)(blockCol + aRow) * K + k0 + aCol);
        Bs[aCol + 0][aRow] = b4.x;
        Bs[aCol + 1][aRow] = b4.y;
        Bs[aCol + 2][aRow] = b4.z;
        Bs[aCol + 3][aRow] = b4.w;
        __syncthreads();

#pragma unroll
        for (int k = 0; k < BK; k++) {
            float regM[TM], regN[TN];
            float4 m0 = *(const float4*)(&As[k][tr * TM]);
            float4 m1 = *(const float4*)(&As[k][tr * TM + 4]);
            regM[0]=m0.x; regM[1]=m0.y; regM[2]=m0.z; regM[3]=m0.w;
            regM[4]=m1.x; regM[5]=m1.y; regM[6]=m1.z; regM[7]=m1.w;
            float4 n0 = *(const float4*)(&Bs[k][tc * TN]);
            float4 n1 = *(const float4*)(&Bs[k][tc * TN + 4]);
            regN[0]=n0.x; regN[1]=n0.y; regN[2]=n0.z; regN[3]=n0.w;
            regN[4]=n1.x; regN[5]=n1.y; regN[6]=n1.z; regN[7]=n1.w;
#pragma unroll
            for (int i = 0; i < TM; i++)
#pragma unroll
                for (int j = 0; j < TN; j++)
                    acc[i][j] += regM[i] * regN[j];
        }
        __syncthreads();
    }

#pragma unroll
    for (int i = 0; i < TM; i++) {
        int row = blockRow + tr * TM + i;
        float4 c0 = make_float4(acc[i][0], acc[i][1], acc[i][2], acc[i][3]);
        float4 c1 = make_float4(acc[i][4], acc[i][5], acc[i][6], acc[i][7]);
        *(float4*)(C + (size_t)row * N + blockCol + tc * TN)     = c0;
        *(float4*)(C + (size_t)row * N + blockCol + tc * TN + 4) = c1;
    }
}

// ---------------- RoPE (first 64 dims of each head) ----------------------
// x: [MROWS, nheads*192]; position = row % SEQ (position_ids is arange).
__global__ void rope_kernel(float* __restrict__ x, int nheads, int total)
{
    int i = blockIdx.x * blockDim.x + threadIdx.x;
    if (i >= total) return;
    int d   = i & 31;
    int h   = (i >> 5) % nheads;
    int row = i / (32 * nheads);
    int s   = row & (SEQ - 1);

    // inv_freq = theta^(-d/32); log2(5e6) = 22.253496664211536
    double inv = exp2(-(double)d * (22.253496664211536 / 32.0));
    float ang  = (float)((double)s * inv);
    float sn, cs;
    sincosf(ang, &sn, &cs);

    float* p = x + (size_t)row * nheads * QKD + h * QKD;
    float x1 = p[d], x2 = p[d + 32];
    p[d]      = x1 * cs - x2 * sn;
    p[d + 32] = x2 * cs + x1 * sn;
}

// ---------------- Flash attention (fp32, causal, GQA) ---------------------
// Block: one (batch, head, 64-query tile). 256 threads = 64 rows x 4 "quad".
// Each thread: 16 score cols (c = 4*j + quad), 32 output cols (quad*32..+31).
#define BQ      64
#define BKV     64
#define KSTRIDE 196   // 192 padded to kill LDS bank conflicts (float4 aligned)

__global__ __launch_bounds__(256)
void flash_kernel(const float* __restrict__ Q, const float* __restrict__ K,
                  const float* __restrict__ V, float* __restrict__ O)
{
    extern __shared__ float sm[];
    float* Qs = sm;                      // [64][196]
    float* Ks = Qs + BQ * KSTRIDE;       // [64][196]
    float* Vs = Ks + BKV * KSTRIDE;      // [64][128]
    float* Ss = Vs + BKV * VDIM;         // [64][65]

    const int qt = blockIdx.x;           // 0..31
    const int h  = blockIdx.y;           // 0..31
    const int b  = blockIdx.z;           // 0..1
    const int kh = h >> 3;

    const int tid  = threadIdx.x;
    const int r    = tid >> 2;           // 0..63
    const int quad = tid & 3;

    // load Q tile (64 x 192)
    const size_t qbase = ((size_t)(b * SEQ + qt * BQ)) * QCOLS + (size_t)h * QKD;
    for (int i = tid; i < BQ * 48; i += 256) {
        int row = i / 48, c4 = i % 48;
        *(float4*)(Qs + row * KSTRIDE + c4 * 4) =
            *(const float4*)(Q + qbase + (size_t)row * QCOLS + c4 * 4);
    }

    float m = -INFINITY, l = 0.f;
    float acc[32];
#pragma unroll
    for (int i = 0; i < 32; i++) acc[i] = 0.f;

    const int   qglob = qt * BQ + r;
    const float scale = 0.07216878364870323f;  // 1/sqrt(192)
    const int   nkt   = qt + 1;                // causal tile skip

    for (int kt = 0; kt < nkt; kt++) {
        __syncthreads();  // previous-iter Vs/Ss reads done; Qs ready on iter 0
        const size_t kbase = ((size_t)(b * SEQ + kt * BKV)) * KCOLS + (size_t)kh * QKD;
        for (int i = tid; i < BKV * 48; i += 256) {
            int row = i / 48, c4 = i % 48;
            *(float4*)(Ks + row * KSTRIDE + c4 * 4) =
                *(const float4*)(K + kbase + (size_t)row * KCOLS + c4 * 4);
        }
        const size_t vbase = ((size_t)(b * SEQ + kt * BKV)) * VCOLS + (size_t)kh * VDIM;
        for (int i = tid; i < BKV * 32; i += 256) {
            int row = i / 32, c4 = i % 32;
            *(float4*)(Vs + row * VDIM + c4 * 4) =
                *(const float4*)(V + vbase + (size_t)row * VCOLS + c4 * 4);
        }
        __syncthreads();

        // ---- scores: s[j] = Q[r] . K[4j+quad] ----
        float s[16];
#pragma unroll
        for (int j = 0; j < 16; j++) s[j] = 0.f;
        const float4* Q4 = (const float4*)(Qs + r * KSTRIDE);
#pragma unroll 4
        for (int d4 = 0; d4 < 48; d4++) {
            float4 qv = Q4[d4];
#pragma unroll
            for (int j = 0; j < 16; j++) {
                float4 kv = *(const float4*)(Ks + (4 * j + quad) * KSTRIDE + d4 * 4);
                s[j] += qv.x * kv.x + qv.y * kv.y + qv.z * kv.z + qv.w * kv.w;
            }
        }

        // ---- mask + online softmax ----
        float tmax = -INFINITY;
#pragma unroll
        for (int j = 0; j < 16; j++) {
            int kg = kt * BKV + 4 * j + quad;
            s[j] = (kg <= qglob) ? s[j] * scale : -INFINITY;
            tmax = fmaxf(tmax, s[j]);
        }
        tmax = fmaxf(tmax, __shfl_xor_sync(0xffffffffu, tmax, 1));
        tmax = fmaxf(tmax, __shfl_xor_sync(0xffffffffu, tmax, 2));
        float mnew = fmaxf(m, tmax);
        float corr = __expf(m - mnew);

        float psum = 0.f;
#pragma unroll
        for (int j = 0; j < 16; j++) {
            float p = __expf(s[j] - mnew);
            psum += p;
            Ss[r * 65 + 4 * j + quad] = p;
        }
        psum += __shfl_xor_sync(0xffffffffu, psum, 1);
        psum += __shfl_xor_sync(0xffffffffu, psum, 2);
        l = l * corr + psum;
        m = mnew;
#pragma unroll
        for (int i = 0; i < 32; i++) acc[i] *= corr;
        __syncwarp();  // Ss row r written/read only within this warp

        // ---- PV: acc[quad*32 + i] += sum_c P[r][c] * V[c][quad*32+i] ----
#pragma unroll 2
        for (int c = 0; c < BKV; c++) {
            float p = Ss[r * 65 + c];
            const float4* V4 = (const float4*)(Vs + c * VDIM + quad * 32);
#pragma unroll
            for (int i2 = 0; i2 < 8; i2++) {
                float4 vv = V4[i2];
                acc[4 * i2 + 0] += p * vv.x;
                acc[4 * i2 + 1] += p * vv.y;
                acc[4 * i2 + 2] += p * vv.z;
                acc[4 * i2 + 3] += p * vv.w;
            }
        }
    }

    // ---- normalize & store to g_att [row][h*128 + col] ----
    float inv_l = 1.0f / l;
    float* outp = O + ((size_t)(b * SEQ + qt * BQ + r)) * OCOLS + h * VDIM + quad * 32;
#pragma unroll
    for (int i2 = 0; i2 < 8; i2++) {
        float4 o;
        o.x = acc[4 * i2 + 0] * inv_l;
        o.y = acc[4 * i2 + 1] * inv_l;
        o.z = acc[4 * i2 + 2] * inv_l;
        o.w = acc[4 * i2 + 3] * inv_l;
        *(float4*)(outp + i2 * 4) = o;
    }
}

// ---------------- launch ----------------
extern "C" void kernel_launch(void* const* d_in, const int* in_sizes, int n_in,
                              void* d_out, int out_size)
{
    const float* hs = (const float*)d_in[0];
    // d_in[1] = attention_mask (pure causal -> applied analytically)
    // d_in[2] = position_ids   (arange -> applied analytically)
    const float* wq = (const float*)d_in[3];
    const float* wk = (const float*)d_in[4];
    const float* wv = (const float*)d_in[5];
    const float* wo = (const float*)d_in[6];
    float* out = (float*)d_out;

    float *qb, *kb, *vb, *ab;
    cudaGetSymbolAddress((void**)&qb, g_q);
    cudaGetSymbolAddress((void**)&kb, g_k);
    cudaGetSymbolAddress((void**)&vb, g_v);
    cudaGetSymbolAddress((void**)&ab, g_att);

    const int FLASH_SMEM = (BQ * KSTRIDE + BKV * KSTRIDE + BKV * VDIM + BQ * 65) * 4;
    cudaFuncSetAttribute(flash_kernel, cudaFuncAttributeMaxDynamicSharedMemorySize,
                         FLASH_SMEM);

    dim3 blk(256);
    // projections
    sgemm_tn<<<dim3(QCOLS / 128, MROWS / 128), blk>>>(hs, wq, qb, MROWS, QCOLS, HIDDEN);
    sgemm_tn<<<dim3(KCOLS / 128, MROWS / 128), blk>>>(hs, wk, kb, MROWS, KCOLS, HIDDEN);
    sgemm_tn<<<dim3(VCOLS / 128, MROWS / 128), blk>>>(hs, wv, vb, MROWS, VCOLS, HIDDEN);
    // rope
    {
        int tq = MROWS * NH * 32;
        int tk = MROWS * NKV * 32;
        rope_kernel<<<(tq + 255) / 256, 256>>>(qb, NH, tq);
        rope_kernel<<<(tk + 255) / 256, 256>>>(kb, NKV, tk);
    }
    // attention
    flash_kernel<<<dim3(SEQ / BQ, NH, BATCH), 256, FLASH_SMEM>>>(qb, kb, vb, ab);
    // output projection
    sgemm_tn<<<dim3(OCOLS / 128, MROWS / 128), blk>>>(ab, wo, out, MROWS, OCOLS, HIDDEN);
}

// round 2
// speedup vs baseline: 1.5020x; 1.5020x over previous
#include <cuda_runtime.h>
#include <cuda_bf16.h>
#include <math.h>

// ---------------- problem constants ----------------
#define BATCH   2
#define SEQ     2048
#define HIDDEN  4096
#define NH      32
#define NKV     4
#define QKD     192
#define VDIM    128
#define MROWS   (BATCH*SEQ)          // 4096
#define QCOLS   (NH*QKD)             // 6144
#define KCOLS   (NKV*QKD)            // 768
#define VCOLS   (NKV*VDIM)           // 512
#define OCOLS   (NH*VDIM)            // 4096

// ---------------- scratch (device globals: allocation-free) ----------------
__device__ float g_q[(size_t)MROWS * QCOLS];    // ~100 MB
__device__ float g_k[(size_t)MROWS * KCOLS];    // ~12.6 MB
__device__ float g_v[(size_t)MROWS * VCOLS];    // ~8.4 MB
__device__ float g_att[(size_t)MROWS * OCOLS];  // ~67 MB

// ---------------- helpers ----------------
__device__ __forceinline__ unsigned f2tf32(float x) {
    unsigned u;
    asm("cvt.rna.tf32.f32 %0, %1;" : "=r"(u) : "f"(x));
    return u;
}

// ---------------- tf32 tensor-core GEMM: C[M,N] = A[M,K] * B[N,K]^T -------
// BM=BN=128, BK=16, 256 threads = 8 warps (2x4), warp tile 64x32.
// mma.sync.aligned.m16n8k8.row.col.f32.tf32.tf32.f32, cp.async double buffer.
__global__ __launch_bounds__(256)
void gemm_tf32(const float* __restrict__ A, const float* __restrict__ B,
               float* __restrict__ C, int M, int N, int K)
{
    __shared__ float As[2][128][20];   // 16 cols data + 4 pad (stride 20: conflict-free)
    __shared__ float Bs[2][128][20];

    const int tid  = threadIdx.x;
    const int lane = tid & 31;
    const int wid  = tid >> 5;
    const int warpM = (wid >> 2) << 6;   // 0 or 64
    const int warpN = (wid & 3) << 5;    // 0,32,64,96
    const int gr = lane >> 2;            // 0..7
    const int tg = lane & 3;             // 0..3

    const int blockRow = blockIdx.y * 128;
    const int blockCol = blockIdx.x * 128;

    const int lrow = tid >> 2;           // 0..63
    const int lcol = (tid & 3) << 2;     // 0,4,8,12

    const float* Ag = A + (size_t)(blockRow + lrow) * K + lcol;
    const float* Bg = B + (size_t)(blockCol + lrow) * K + lcol;

    float c[4][4][4];
#pragma unroll
    for (int mt = 0; mt < 4; mt++)
#pragma unroll
        for (int nt = 0; nt < 4; nt++)
#pragma unroll
            for (int i = 0; i < 4; i++) c[mt][nt][i] = 0.f;

#define LOAD_STAGE(s, kb)                                                        \
    do {                                                                         \
        unsigned da0 = (unsigned)__cvta_generic_to_shared(&As[s][lrow][lcol]);   \
        unsigned da1 = (unsigned)__cvta_generic_to_shared(&As[s][lrow+64][lcol]);\
        unsigned db0 = (unsigned)__cvta_generic_to_shared(&Bs[s][lrow][lcol]);   \
        unsigned db1 = (unsigned)__cvta_generic_to_shared(&Bs[s][lrow+64][lcol]);\
        asm volatile("cp.async.ca.shared.global [%0], [%1], 16;" ::              \
                     "r"(da0), "l"(Ag + (kb)));                                  \
        asm volatile("cp.async.ca.shared.global [%0], [%1], 16;" ::              \
                     "r"(da1), "l"(Ag + (size_t)64 * K + (kb)));                 \
        asm volatile("cp.async.ca.shared.global [%0], [%1], 16;" ::              \
                     "r"(db0), "l"(Bg + (kb)));                                  \
        asm volatile("cp.async.ca.shared.global [%0], [%1], 16;" ::              \
                     "r"(db1), "l"(Bg + (size_t)64 * K + (kb)));                 \
        asm volatile("cp.async.commit_group;");                                  \
    } while (0)

    const int NT = K >> 4;    // K/16 tiles
    LOAD_STAGE(0, 0);
    int st = 0;

    for (int t = 0; t < NT; t++) {
        if (t + 1 < NT) {
            LOAD_STAGE(st ^ 1, (t + 1) << 4);
            asm volatile("cp.async.wait_group 1;");
        } else {
            asm volatile("cp.async.wait_group 0;");
        }
        __syncthreads();

#pragma unroll
        for (int ks = 0; ks < 2; ks++) {
            const int k0 = ks << 3;
            unsigned af[4][4], bf[4][2];
#pragma unroll
            for (int mt = 0; mt < 4; mt++) {
                const float* p = &As[st][warpM + mt * 16 + gr][k0 + tg];
                af[mt][0] = f2tf32(p[0]);
                af[mt][1] = f2tf32(p[8 * 20]);
                af[mt][2] = f2tf32(p[4]);
                af[mt][3] = f2tf32(p[8 * 20 + 4]);
            }
#pragma unroll
            for (int nt = 0; nt < 4; nt++) {
                const float* p = &Bs[st][warpN + nt * 8 + gr][k0 + tg];
                bf[nt][0] = f2tf32(p[0]);
                bf[nt][1] = f2tf32(p[4]);
            }
#pragma unroll
            for (int mt = 0; mt < 4; mt++)
#pragma unroll
                for (int nt = 0; nt < 4; nt++) {
                    asm volatile(
                        "mma.sync.aligned.m16n8k8.row.col.f32.tf32.tf32.f32 "
                        "{%0,%1,%2,%3}, {%4,%5,%6,%7}, {%8,%9}, {%0,%1,%2,%3};"
                        : "+f"(c[mt][nt][0]), "+f"(c[mt][nt][1]),
                          "+f"(c[mt][nt][2]), "+f"(c[mt][nt][3])
                        : "r"(af[mt][0]), "r"(af[mt][1]),
                          "r"(af[mt][2]), "r"(af[mt][3]),
                          "r"(bf[nt][0]), "r"(bf[nt][1]));
                }
        }
        __syncthreads();
        st ^= 1;
    }
#undef LOAD_STAGE

    // epilogue: c0,c1 -> (row, col..col+1); c2,c3 -> (row+8, ...)
#pragma unroll
    for (int mt = 0; mt < 4; mt++) {
        int row = blockRow + warpM + mt * 16 + gr;
#pragma unroll
        for (int nt = 0; nt < 4; nt++) {
            int col = blockCol + warpN + nt * 8 + tg * 2;
            float2 v0 = make_float2(c[mt][nt][0], c[mt][nt][1]);
            float2 v1 = make_float2(c[mt][nt][2], c[mt][nt][3]);
            *(float2*)(C + (size_t)row * N + col)       = v0;
            *(float2*)(C + (size_t)(row + 8) * N + col) = v1;
        }
    }
}

// ---------------- RoPE (first 64 dims of each head) ----------------------
__global__ void rope_kernel(float* __restrict__ x, int nheads, int total)
{
    int i = blockIdx.x * blockDim.x + threadIdx.x;
    if (i >= total) return;
    int d   = i & 31;
    int h   = (i >> 5) % nheads;
    int row = i / (32 * nheads);
    int s   = row & (SEQ - 1);

    double inv = exp2(-(double)d * (22.253496664211536 / 32.0));
    float ang  = (float)((double)s * inv);
    float sn, cs;
    sincosf(ang, &sn, &cs);

    float* p = x + (size_t)row * nheads * QKD + h * QKD;
    float x1 = p[d], x2 = p[d + 32];
    p[d]      = x1 * cs - x2 * sn;
    p[d + 32] = x2 * cs + x1 * sn;
}

// ---------------- Flash attention (fp32, causal, GQA) ---------------------
#define BQ      64
#define BKV     64
#define KSTRIDE 196

__global__ __launch_bounds__(256)
void flash_kernel(const float* __restrict__ Q, const float* __restrict__ K,
                  const float* __restrict__ V, float* __restrict__ O)
{
    extern __shared__ float sm[];
    float* Qs = sm;                      // [64][196]
    float* Ks = Qs + BQ * KSTRIDE;       // [64][196]
    float* Vs = Ks + BKV * KSTRIDE;      // [64][128]
    float* Ss = Vs + BKV * VDIM;         // [64][65]

    const int qt = blockIdx.x;
    const int h  = blockIdx.y;
    const int b  = blockIdx.z;
    const int kh = h >> 3;

    const int tid  = threadIdx.x;
    const int r    = tid >> 2;
    const int quad = tid & 3;

    const size_t qbase = ((size_t)(b * SEQ + qt * BQ)) * QCOLS + (size_t)h * QKD;
    for (int i = tid; i < BQ * 48; i += 256) {
        int row = i / 48, c4 = i % 48;
        *(float4*)(Qs + row * KSTRIDE + c4 * 4) =
            *(const float4*)(Q + qbase + (size_t)row * QCOLS + c4 * 4);
    }

    float m = -INFINITY, l = 0.f;
    float acc[32];
#pragma unroll
    for (int i = 0; i < 32; i++) acc[i] = 0.f;

    const int   qglob = qt * BQ + r;
    const float scale = 0.07216878364870323f;
    const int   nkt   = qt + 1;

    for (int kt = 0; kt < nkt; kt++) {
        __syncthreads();
        const size_t kbase = ((size_t)(b * SEQ + kt * BKV)) * KCOLS + (size_t)kh * QKD;
        for (int i = tid; i < BKV * 48; i += 256) {
            int row = i / 48, c4 = i % 48;
            *(float4*)(Ks + row * KSTRIDE + c4 * 4) =
                *(const float4*)(K + kbase + (size_t)row * KCOLS + c4 * 4);
        }
        const size_t vbase = ((size_t)(b * SEQ + kt * BKV)) * VCOLS + (size_t)kh * VDIM;
        for (int i = tid; i < BKV * 32; i += 256) {
            int row = i / 32, c4 = i % 32;
            *(float4*)(Vs + row * VDIM + c4 * 4) =
                *(const float4*)(V + vbase + (size_t)row * VCOLS + c4 * 4);
        }
        __syncthreads();

        float s[16];
#pragma unroll
        for (int j = 0; j < 16; j++) s[j] = 0.f;
        const float4* Q4 = (const float4*)(Qs + r * KSTRIDE);
#pragma unroll 4
        for (int d4 = 0; d4 < 48; d4++) {
            float4 qv = Q4[d4];
#pragma unroll
            for (int j = 0; j < 16; j++) {
                float4 kv = *(const float4*)(Ks + (4 * j + quad) * KSTRIDE + d4 * 4);
                s[j] += qv.x * kv.x + qv.y * kv.y + qv.z * kv.z + qv.w * kv.w;
            }
        }

        float tmax = -INFINITY;
#pragma unroll
        for (int j = 0; j < 16; j++) {
            int kg = kt * BKV + 4 * j + quad;
            s[j] = (kg <= qglob) ? s[j] * scale : -INFINITY;
            tmax = fmaxf(tmax, s[j]);
        }
        tmax = fmaxf(tmax, __shfl_xor_sync(0xffffffffu, tmax, 1));
        tmax = fmaxf(tmax, __shfl_xor_sync(0xffffffffu, tmax, 2));
        float mnew = fmaxf(m, tmax);
        float corr = __expf(m - mnew);

        float psum = 0.f;
#pragma unroll
        for (int j = 0; j < 16; j++) {
            float p = __expf(s[j] - mnew);
            psum += p;
            Ss[r * 65 + 4 * j + quad] = p;
        }
        psum += __shfl_xor_sync(0xffffffffu, psum, 1);
        psum += __shfl_xor_sync(0xffffffffu, psum, 2);
        l = l * corr + psum;
        m = mnew;
#pragma unroll
        for (int i = 0; i < 32; i++) acc[i] *= corr;
        __syncwarp();

#pragma unroll 2
        for (int c = 0; c < BKV; c++) {
            float p = Ss[r * 65 + c];
            const float4* V4 = (const float4*)(Vs + c * VDIM + quad * 32);
#pragma unroll
            for (int i2 = 0; i2 < 8; i2++) {
                float4 vv = V4[i2];
                acc[4 * i2 + 0] += p * vv.x;
                acc[4 * i2 + 1] += p * vv.y;
                acc[4 * i2 + 2] += p * vv.z;
                acc[4 * i2 + 3] += p * vv.w;
            }
        }
    }

    float inv_l = 1.0f / l;
    float* outp = O + ((size_t)(b * SEQ + qt * BQ + r)) * OCOLS + h * VDIM + quad * 32;
#pragma unroll
    for (int i2 = 0; i2 < 8; i2++) {
        float4 o;
        o.x = acc[4 * i2 + 0] * inv_l;
        o.y = acc[4 * i2 + 1] * inv_l;
        o.z = acc[4 * i2 + 2] * inv_l;
        o.w = acc[4 * i2 + 3] * inv_l;
        *(float4*)(outp + i2 * 4) = o;
    }
}

// ---------------- launch ----------------
extern "C" void kernel_launch(void* const* d_in, const int* in_sizes, int n_in,
                              void* d_out, int out_size)
{
    const float* hs = (const float*)d_in[0];
    const float* wq = (const float*)d_in[3];
    const float* wk = (const float*)d_in[4];
    const float* wv = (const float*)d_in[5];
    const float* wo = (const float*)d_in[6];
    float* out = (float*)d_out;

    float *qb, *kb, *vb, *ab;
    cudaGetSymbolAddress((void**)&qb, g_q);
    cudaGetSymbolAddress((void**)&kb, g_k);
    cudaGetSymbolAddress((void**)&vb, g_v);
    cudaGetSymbolAddress((void**)&ab, g_att);

    const int FLASH_SMEM = (BQ * KSTRIDE + BKV * KSTRIDE + BKV * VDIM + BQ * 65) * 4;
    cudaFuncSetAttribute(flash_kernel, cudaFuncAttributeMaxDynamicSharedMemorySize,
                         FLASH_SMEM);

    dim3 blk(256);
    // projections (tensor core tf32)
    gemm_tf32<<<dim3(QCOLS / 128, MROWS / 128), blk>>>(hs, wq, qb, MROWS, QCOLS, HIDDEN);
    gemm_tf32<<<dim3(KCOLS / 128, MROWS / 128), blk>>>(hs, wk, kb, MROWS, KCOLS, HIDDEN);
    gemm_tf32<<<dim3(VCOLS / 128, MROWS / 128), blk>>>(hs, wv, vb, MROWS, VCOLS, HIDDEN);
    // rope
    {
        int tq = MROWS * NH * 32;
        int tk = MROWS * NKV * 32;
        rope_kernel<<<(tq + 255) / 256, 256>>>(qb, NH, tq);
        rope_kernel<<<(tk + 255) / 256, 256>>>(kb, NKV, tk);
    }
    // attention
    flash_kernel<<<dim3(SEQ / BQ, NH, BATCH), 256, FLASH_SMEM>>>(qb, kb, vb, ab);
    // output projection
    gemm_tf32<<<dim3(OCOLS / 128, MROWS / 128), blk>>>(ab, wo, out, MROWS, OCOLS, HIDDEN);
}

// round 4
// speedup vs baseline: 4.7244x; 3.1455x over previous
#include <cuda_runtime.h>
#include <cuda_bf16.h>
#include <math.h>
#include <stdint.h>

// ---------------- problem constants ----------------
#define BATCH   2
#define SEQ     2048
#define HIDDEN  4096
#define NH      32
#define NKV     4
#define QKD     192
#define VDIM    128
#define MROWS   (BATCH*SEQ)          // 4096
#define QCOLS   (NH*QKD)             // 6144
#define KCOLS   (NKV*QKD)            // 768
#define VCOLS   (NKV*VDIM)           // 512
#define OCOLS   (NH*VDIM)            // 4096

// ---------------- scratch (device globals: allocation-free) ----------------
__device__ float g_q  [(size_t)MROWS * QCOLS];
__device__ float g_k  [(size_t)MROWS * KCOLS];
__device__ float g_v  [(size_t)MROWS * VCOLS];
__device__ float g_att[(size_t)MROWS * OCOLS];
// tf32-rounded (rna) operands
__device__ float g_hs [(size_t)MROWS * HIDDEN];
__device__ float g_wq [(size_t)QCOLS * HIDDEN];
__device__ float g_wk [(size_t)KCOLS * HIDDEN];
__device__ float g_wv [(size_t)VCOLS * HIDDEN];
__device__ float g_wo [(size_t)HIDDEN * OCOLS];

// ---------------- helpers ----------------
__device__ __forceinline__ float f2tf32(float x) {
    uint32_t u;
    asm("cvt.rna.tf32.f32 %0, %1;" : "=r"(u) : "f"(x));
    return __uint_as_float(u);
}

// mma.sync m16n8k8 tf32: operands are fp32 bit patterns already rounded to tf32
__device__ __forceinline__ void mma_tf32(float c[4],
                                         float a0, float a1, float a2, float a3,
                                         float b0, float b1)
{
    asm volatile(
        "mma.sync.aligned.m16n8k8.row.col.f32.tf32.tf32.f32 "
        "{%0,%1,%2,%3}, {%4,%5,%6,%7}, {%8,%9}, {%0,%1,%2,%3};"
        : "+f"(c[0]), "+f"(c[1]), "+f"(c[2]), "+f"(c[3])
        : "r"(__float_as_uint(a0)), "r"(__float_as_uint(a1)),
          "r"(__float_as_uint(a2)), "r"(__float_as_uint(a3)),
          "r"(__float_as_uint(b0)), "r"(__float_as_uint(b1)));
}

// ---------------- tf32 rounding pre-pass ----------------
__global__ void round_tf32_kernel(const float* __restrict__ in, float* __restrict__ out,
                                  size_t n4)
{
    size_t i = (size_t)blockIdx.x * blockDim.x + threadIdx.x;
    if (i >= n4) return;
    float4 v = ((const float4*)in)[i];
    v.x = f2tf32(v.x); v.y = f2tf32(v.y); v.z = f2tf32(v.z); v.w = f2tf32(v.w);
    ((float4*)out)[i] = v;
}

// ---------------- tf32 tensor-core GEMM: C[M,N] = A[M,K] * B[N,K]^T -------
// BM=BN=128, BK=16, 256 threads = 8 warps (2x4), warp tile 64x32.
// Operands pre-rounded to tf32 -> no cvt in the hot loop.
__global__ __launch_bounds__(256)
void gemm_tf32(const float* __restrict__ A, const float* __restrict__ B,
               float* __restrict__ C, int M, int N, int K, int round_out)
{
    __shared__ float As[2][128][20];
    __shared__ float Bs[2][128][20];

    const int tid  = threadIdx.x;
    const int lane = tid & 31;
    const int wid  = tid >> 5;
    const int warpM = (wid >> 2) << 6;
    const int warpN = (wid & 3) << 5;
    const int gr = lane >> 2;
    const int tg = lane & 3;

    const int blockRow = blockIdx.y * 128;
    const int blockCol = blockIdx.x * 128;

    const int lrow = tid >> 2;
    const int lcol = (tid & 3) << 2;

    const float* Ag = A + (size_t)(blockRow + lrow) * K + lcol;
    const float* Bg = B + (size_t)(blockCol + lrow) * K + lcol;

    float c[4][4][4];
#pragma unroll
    for (int mt = 0; mt < 4; mt++)
#pragma unroll
        for (int nt = 0; nt < 4; nt++)
#pragma unroll
            for (int i = 0; i < 4; i++) c[mt][nt][i] = 0.f;

#define LOAD_STAGE(s, kb)                                                        \
    do {                                                                         \
        unsigned da0 = (unsigned)__cvta_generic_to_shared(&As[s][lrow][lcol]);   \
        unsigned da1 = (unsigned)__cvta_generic_to_shared(&As[s][lrow+64][lcol]);\
        unsigned db0 = (unsigned)__cvta_generic_to_shared(&Bs[s][lrow][lcol]);   \
        unsigned db1 = (unsigned)__cvta_generic_to_shared(&Bs[s][lrow+64][lcol]);\
        asm volatile("cp.async.ca.shared.global [%0], [%1], 16;" ::              \
                     "r"(da0), "l"(Ag + (kb)));                                  \
        asm volatile("cp.async.ca.shared.global [%0], [%1], 16;" ::              \
                     "r"(da1), "l"(Ag + (size_t)64 * K + (kb)));                 \
        asm volatile("cp.async.ca.shared.global [%0], [%1], 16;" ::              \
                     "r"(db0), "l"(Bg + (kb)));                                  \
        asm volatile("cp.async.ca.shared.global [%0], [%1], 16;" ::              \
                     "r"(db1), "l"(Bg + (size_t)64 * K + (kb)));                 \
        asm volatile("cp.async.commit_group;");                                  \
    } while (0)

    const int NT = K >> 4;
    LOAD_STAGE(0, 0);
    int st = 0;

    for (int t = 0; t < NT; t++) {
        if (t + 1 < NT) {
            LOAD_STAGE(st ^ 1, (t + 1) << 4);
            asm volatile("cp.async.wait_group 1;");
        } else {
            asm volatile("cp.async.wait_group 0;");
        }
        __syncthreads();

#pragma unroll
        for (int ks = 0; ks < 2; ks++) {
            const int k0 = ks << 3;
            float af[4][4], bf[4][2];
#pragma unroll
            for (int mt = 0; mt < 4; mt++) {
                const float* p = &As[st][warpM + mt * 16 + gr][k0 + tg];
                af[mt][0] = p[0];
                af[mt][1] = p[8 * 20];
                af[mt][2] = p[4];
                af[mt][3] = p[8 * 20 + 4];
            }
#pragma unroll
            for (int nt = 0; nt < 4; nt++) {
                const float* p = &Bs[st][warpN + nt * 8 + gr][k0 + tg];
                bf[nt][0] = p[0];
                bf[nt][1] = p[4];
            }
#pragma unroll
            for (int mt = 0; mt < 4; mt++)
#pragma unroll
                for (int nt = 0; nt < 4; nt++)
                    mma_tf32(c[mt][nt], af[mt][0], af[mt][1], af[mt][2], af[mt][3],
                             bf[nt][0], bf[nt][1]);
        }
        __syncthreads();
        st ^= 1;
    }
#undef LOAD_STAGE

#pragma unroll
    for (int mt = 0; mt < 4; mt++) {
        int row = blockRow + warpM + mt * 16 + gr;
#pragma unroll
        for (int nt = 0; nt < 4; nt++) {
            int col = blockCol + warpN + nt * 8 + tg * 2;
            float v0 = c[mt][nt][0], v1 = c[mt][nt][1];
            float v2 = c[mt][nt][2], v3 = c[mt][nt][3];
            if (round_out) {
                v0 = f2tf32(v0); v1 = f2tf32(v1);
                v2 = f2tf32(v2); v3 = f2tf32(v3);
            }
            *(float2*)(C + (size_t)row * N + col)       = make_float2(v0, v1);
            *(float2*)(C + (size_t)(row + 8) * N + col) = make_float2(v2, v3);
        }
    }
}

// ---------------- RoPE (first 64 dims of each head), tf32-rounded out ----
__global__ void rope_kernel(float* __restrict__ x, int nheads, int total)
{
    int i = blockIdx.x * blockDim.x + threadIdx.x;
    if (i >= total) return;
    int d   = i & 31;
    int h   = (i >> 5) % nheads;
    int row = i / (32 * nheads);
    int s   = row & (SEQ - 1);

    double inv = exp2(-(double)d * (22.253496664211536 / 32.0));
    float ang  = (float)((double)s * inv);
    float sn, cs;
    sincosf(ang, &sn, &cs);

    float* p = x + (size_t)row * nheads * QKD + h * QKD;
    float x1 = p[d], x2 = p[d + 32];
    p[d]      = f2tf32(x1 * cs - x2 * sn);
    p[d + 32] = f2tf32(x2 * cs + x1 * sn);
}

// ---------------- Flash attention v2: tensor-core QK^T and PV ------------
// 64x64 tiles, 256 threads = 8 warps.
// Scores: warp w -> rows [16*(w&3), +16), cols [32*(w>>2), +32)
// PV:     warp w -> rows [16*(w&3), +16), cols [64*(w>>2), +64)
// Softmax: thread roles r=tid>>2 (row), quad=tid&3 (cols 4j+quad), as before.
#define FQS 196   // Qs/Ks row stride (floats)
#define FVS 132   // Vs row stride
#define FSS 68    // Ss row stride
#define FLASH2_FLOATS (64*FQS + 64*FQS + 64*FVS + 64*FSS + 64 + 64)
#define FLASH2_SMEM   (FLASH2_FLOATS * 4)

__global__ __launch_bounds__(256)
void flash2_kernel(const float* __restrict__ Q, const float* __restrict__ K,
                   const float* __restrict__ V, float* __restrict__ O)
{
    extern __shared__ float sm[];
    float* Qs    = sm;
    float* Ks    = Qs + 64 * FQS;
    float* Vs    = Ks + 64 * FQS;
    float* Ss    = Vs + 64 * FVS;
    float* scorr = Ss + 64 * FSS;
    float* slinv = scorr + 64;

    const int qt = blockIdx.x;
    const int h  = blockIdx.y;
    const int b  = blockIdx.z;
    const int kh = h >> 3;

    const int tid  = threadIdx.x;
    const int wid  = tid >> 5;
    const int lane = tid & 31;
    const int gr   = lane >> 2;
    const int tg   = lane & 3;
    const int rs   = wid & 3;        // row strip
    const int ch   = wid >> 2;       // col half

    const int r    = tid >> 2;       // softmax row
    const int quad = tid & 3;

    // ---- load Q tile (64 x 192), values already tf32-rounded ----
    const size_t qbase = ((size_t)(b * SEQ + qt * 64)) * QCOLS + (size_t)h * QKD;
    for (int i = tid; i < 64 * 48; i += 256) {
        int row = i / 48, c4 = i % 48;
        *(float4*)(Qs + row * FQS + c4 * 4) =
            *(const float4*)(Q + qbase + (size_t)row * QCOLS + c4 * 4);
    }

    float m = -INFINITY, l = 0.f;
    float acc[8][4];
#pragma unroll
    for (int nt = 0; nt < 8; nt++)
#pragma unroll
        for (int i = 0; i < 4; i++) acc[nt][i] = 0.f;

    const int   qglob = qt * 64 + r;
    const float scale = 0.07216878364870323f;   // 1/sqrt(192)
    const int   nkt   = qt + 1;

    // hoisted fragment base pointers
    const float* Qr0 = Qs + (16 * rs + gr) * FQS + tg;      // rows gr / gr+8 via +8*FQS
    const float* Kb  = Ks + (32 * ch + gr) * FQS + tg;      // + nt*8*FQS
    const float* Pr0 = Ss + (16 * rs + gr) * FSS + tg;
    const float* Vb  = Vs + tg * FVS + 64 * ch + gr;        // + k0*FVS + nt*8

    for (int kt = 0; kt < nkt; kt++) {
        __syncthreads();   // S1: prior consumers of Ks/Vs/Ss done

        // ---- load K (64x192) and V (64x128) tiles ----
        const size_t kbase = ((size_t)(b * SEQ + kt * 64)) * KCOLS + (size_t)kh * QKD;
        for (int i = tid; i < 64 * 48; i += 256) {
            int row = i / 48, c4 = i % 48;
            *(float4*)(Ks + row * FQS + c4 * 4) =
                *(const float4*)(K + kbase + (size_t)row * KCOLS + c4 * 4);
        }
        const size_t vbase = ((size_t)(b * SEQ + kt * 64)) * VCOLS + (size_t)kh * VDIM;
        for (int i = tid; i < 64 * 32; i += 256) {
            int row = i / 32, c4 = i % 32;
            *(float4*)(Vs + row * FVS + c4 * 4) =
                *(const float4*)(V + vbase + (size_t)row * VCOLS + c4 * 4);
        }
        __syncthreads();   // S2: tiles ready

        // ---- scores: S[16 rows][32 cols] per warp via mma ----
        float cf[4][4];
#pragma unroll
        for (int nt = 0; nt < 4; nt++)
#pragma unroll
            for (int i = 0; i < 4; i++) cf[nt][i] = 0.f;

#pragma unroll 4
        for (int ktile = 0; ktile < 24; ktile++) {
            const int k0 = ktile * 8;
            float a0 = Qr0[k0],           a1 = Qr0[k0 + 8 * FQS];
            float a2 = Qr0[k0 + 4],       a3 = Qr0[k0 + 8 * FQS + 4];
#pragma unroll
            for (int nt = 0; nt < 4; nt++) {
                const float* kp = Kb + nt * 8 * FQS + k0;
                mma_tf32(cf[nt], a0, a1, a2, a3, kp[0], kp[4]);
            }
        }
        // write S fragments to smem
        {
            float* s0 = Ss + (16 * rs + gr) * FSS + 32 * ch + 2 * tg;
#pragma unroll
            for (int nt = 0; nt < 4; nt++) {
                *(float2*)(s0 + nt * 8)            = make_float2(cf[nt][0], cf[nt][1]);
                *(float2*)(s0 + nt * 8 + 8 * FSS)  = make_float2(cf[nt][2], cf[nt][3]);
            }
        }
        __syncthreads();   // S3: all scores in smem

        // ---- online softmax (row-parallel, 4 threads per row) ----
        {
            float* Srow = Ss + r * FSS;
            float s[16];
            float tmax = -INFINITY;
#pragma unroll
            for (int j = 0; j < 16; j++) {
                int cg = kt * 64 + 4 * j + quad;
                float v = Srow[4 * j + quad] * scale;
                s[j] = (cg <= qglob) ? v : -INFINITY;
                tmax = fmaxf(tmax, s[j]);
            }
            tmax = fmaxf(tmax, __shfl_xor_sync(0xffffffffu, tmax, 1));
            tmax = fmaxf(tmax, __shfl_xor_sync(0xffffffffu, tmax, 2));
            float mnew = fmaxf(m, tmax);
            float corr = __expf(m - mnew);

            float psum = 0.f;
#pragma unroll
            for (int j = 0; j < 16; j++) {
                float p = f2tf32(__expf(s[j] - mnew));
                psum += p;
                Srow[4 * j + quad] = p;
            }
            psum += __shfl_xor_sync(0xffffffffu, psum, 1);
            psum += __shfl_xor_sync(0xffffffffu, psum, 2);
            l = l * corr + psum;
            m = mnew;
            if (quad == 0) scorr[r] = corr;
        }
        __syncthreads();   // S4: P + corr ready

        // ---- PV: O[16 rows][64 cols] per warp via mma, with rescale ----
        {
            float ca = scorr[16 * rs + gr];
            float cb = scorr[16 * rs + gr + 8];
#pragma unroll
            for (int nt = 0; nt < 8; nt++) {
                acc[nt][0] *= ca; acc[nt][1] *= ca;
                acc[nt][2] *= cb; acc[nt][3] *= cb;
            }
#pragma unroll
            for (int ktile = 0; ktile < 8; ktile++) {
                const int k0 = ktile * 8;
                float a0 = Pr0[k0],     a1 = Pr0[k0 + 8 * FSS];
                float a2 = Pr0[k0 + 4], a3 = Pr0[k0 + 8 * FSS + 4];
                const float* vp = Vb + k0 * FVS;
#pragma unroll
                for (int nt = 0; nt < 8; nt++)
                    mma_tf32(acc[nt], a0, a1, a2, a3,
                             vp[nt * 8], vp[nt * 8 + 4 * FVS]);
            }
        }
    }

    // ---- final: normalize and store (rounded tf32 for the wo GEMM) ----
    if (quad == 0) slinv[r] = 1.0f / l;
    __syncthreads();

    const int row0 = 16 * rs + gr;
    const float inv0 = slinv[row0];
    const float inv1 = slinv[row0 + 8];
    float* o0 = O + ((size_t)(b * SEQ + qt * 64 + row0)) * OCOLS
                  + h * VDIM + 64 * ch + 2 * tg;
#pragma unroll
    for (int nt = 0; nt < 8; nt++) {
        *(float2*)(o0 + nt * 8) =
            make_float2(f2tf32(acc[nt][0] * inv0), f2tf32(acc[nt][1] * inv0));
        *(float2*)(o0 + nt * 8 + 8 * OCOLS) =
            make_float2(f2tf32(acc[nt][2] * inv1), f2tf32(acc[nt][3] * inv1));
    }
}

// ---------------- launch ----------------
extern "C" void kernel_launch(void* const* d_in, const int* in_sizes, int n_in,
                              void* d_out, int out_size)
{
    const float* hs = (const float*)d_in[0];
    const float* wq = (const float*)d_in[3];
    const float* wk = (const float*)d_in[4];
    const float* wv = (const float*)d_in[5];
    const float* wo = (const float*)d_in[6];
    float* out = (float*)d_out;

    float *qb, *kb, *vb, *ab, *hsr, *wqr, *wkr, *wvr, *wor;
    cudaGetSymbolAddress((void**)&qb, g_q);
    cudaGetSymbolAddress((void**)&kb, g_k);
    cudaGetSymbolAddress((void**)&vb, g_v);
    cudaGetSymbolAddress((void**)&ab, g_att);
    cudaGetSymbolAddress((void**)&hsr, g_hs);
    cudaGetSymbolAddress((void**)&wqr, g_wq);
    cudaGetSymbolAddress((void**)&wkr, g_wk);
    cudaGetSymbolAddress((void**)&wvr, g_wv);
    cudaGetSymbolAddress((void**)&wor, g_wo);

    cudaFuncSetAttribute(flash2_kernel, cudaFuncAttributeMaxDynamicSharedMemorySize,
                         FLASH2_SMEM);

    // tf32 rna pre-rounding of GEMM operands
    {
        size_t n;
        n = (size_t)MROWS * HIDDEN / 4;
        round_tf32_kernel<<<(unsigned)((n + 255) / 256), 256>>>(hs, hsr, n);
        n = (size_t)QCOLS * HIDDEN / 4;
        round_tf32_kernel<<<(unsigned)((n + 255) / 256), 256>>>(wq, wqr, n);
        n = (size_t)KCOLS * HIDDEN / 4;
        round_tf32_kernel<<<(unsigned)((n + 255) / 256), 256>>>(wk, wkr, n);
        n = (size_t)VCOLS * HIDDEN / 4;
        round_tf32_kernel<<<(unsigned)((n + 255) / 256), 256>>>(wv, wvr, n);
        n = (size_t)HIDDEN * OCOLS / 4;
        round_tf32_kernel<<<(unsigned)((n + 255) / 256), 256>>>(wo, wor, n);
    }

    dim3 blk(256);
    // projections (round outputs to tf32 for downstream mma)
    gemm_tf32<<<dim3(QCOLS / 128, MROWS / 128), blk>>>(hsr, wqr, qb, MROWS, QCOLS, HIDDEN, 1);
    gemm_tf32<<<dim3(KCOLS / 128, MROWS / 128), blk>>>(hsr, wkr, kb, MROWS, KCOLS, HIDDEN, 1);
    gemm_tf32<<<dim3(VCOLS / 128, MROWS / 128), blk>>>(hsr, wvr, vb, MROWS, VCOLS, HIDDEN, 1);
    // rope (re-rounds rotated dims)
    {
        int tq = MROWS * NH * 32;
        int tk = MROWS * NKV * 32;
        rope_kernel<<<(tq + 255) / 256, 256>>>(qb, NH, tq);
        rope_kernel<<<(tk + 255) / 256, 256>>>(kb, NKV, tk);
    }
    // attention (tensor-core)
    flash2_kernel<<<dim3(SEQ / 64, NH, BATCH), 256, FLASH2_SMEM>>>(qb, kb, vb, ab);
    // output projection (fp32 out)
    gemm_tf32<<<dim3(OCOLS / 128, MROWS / 128), blk>>>(ab, wor, out, MROWS, OCOLS, HIDDEN, 0);
}

// round 6
// speedup vs baseline: 7.8050x; 1.6521x over previous
#include <cuda_runtime.h>
#include <cuda_fp16.h>
#include <math.h>
#include <stdint.h>

// ---------------- problem constants ----------------
#define BATCH   2
#define SEQ     2048
#define HIDDEN  4096
#define NH      32
#define NKV     4
#define QKD     192
#define VDIM    128
#define MROWS   (BATCH*SEQ)          // 4096
#define QCOLS   (NH*QKD)             // 6144
#define KCOLS   (NKV*QKD)            // 768
#define VCOLS   (NKV*VDIM)           // 512
#define OCOLS   (NH*VDIM)            // 4096

// ---------------- scratch (device globals: allocation-free) ----------------
__device__ __half g_q  [(size_t)MROWS * QCOLS];
__device__ __half g_k  [(size_t)MROWS * KCOLS];
__device__ __half g_v  [(size_t)MROWS * VCOLS];
__device__ __half g_vt [(size_t)BATCH * NKV * VDIM * SEQ];
__device__ __half g_att[(size_t)MROWS * OCOLS];
// fp16-converted GEMM operands
__device__ __half g_hs [(size_t)MROWS * HIDDEN];
__device__ __half g_wq [(size_t)QCOLS * HIDDEN];
__device__ __half g_wk [(size_t)KCOLS * HIDDEN];
__device__ __half g_wv [(size_t)VCOLS * HIDDEN];
__device__ __half g_wo [(size_t)HIDDEN * OCOLS];

// ---------------- helpers ----------------
// fp16 mma m16n8k16, fp32 accumulate
__device__ __forceinline__ void mma_f16(float c[4], uint32_t a0, uint32_t a1,
                                        uint32_t a2, uint32_t a3,
                                        uint32_t b0, uint32_t b1)
{
    asm volatile(
        "mma.sync.aligned.m16n8k16.row.col.f32.f16.f16.f32 "
        "{%0,%1,%2,%3}, {%4,%5,%6,%7}, {%8,%9}, {%0,%1,%2,%3};"
        : "+f"(c[0]), "+f"(c[1]), "+f"(c[2]), "+f"(c[3])
        : "r"(a0), "r"(a1), "r"(a2), "r"(a3), "r"(b0), "r"(b1));
}
__device__ __forceinline__ uint32_t ldh2(const __half* p) {
    return *(const uint32_t*)p;
}

// ---------------- fp32 -> fp16 conversion pass ----------------
__global__ void tohalf_kernel(const float* __restrict__ in, __half* __restrict__ out,
                              size_t n4)
{
    size_t i = (size_t)blockIdx.x * blockDim.x + threadIdx.x;
    if (i >= n4) return;
    float4 v = ((const float4*)in)[i];
    __half2* o = (__half2*)out + 2 * i;
    o[0] = __floats2half2_rn(v.x, v.y);
    o[1] = __floats2half2_rn(v.z, v.w);
}

// ---------------- fp16 tensor-core GEMM: C[M,N] = A[M,K] * B[N,K]^T -------
// BM=BN=128, BK=32, 256 threads = 8 warps (2x4), warp tile 64x32, 2-stage.
__global__ __launch_bounds__(256)
void gemm_h(const __half* __restrict__ A, const __half* __restrict__ B,
            void* __restrict__ Cv, int M, int N, int K, int out_half)
{
    __shared__ __half As[2][128][40];   // 32 data + 8 pad halfs (conflict-free)
    __shared__ __half Bs[2][128][40];

    const int tid  = threadIdx.x;
    const int lane = tid & 31;
    const int wid  = tid >> 5;
    const int warpM = (wid >> 2) << 6;
    const int warpN = (wid & 3) << 5;
    const int gr = lane >> 2;
    const int tg = lane & 3;

    const int blockRow = blockIdx.y * 128;
    const int blockCol = blockIdx.x * 128;

    float c[4][4][4];
#pragma unroll
    for (int mt = 0; mt < 4; mt++)
#pragma unroll
        for (int nt = 0; nt < 4; nt++)
#pragma unroll
            for (int i = 0; i < 4; i++) c[mt][nt][i] = 0.f;

#define LOAD_STAGE(s, kb)                                                          \
    do {                                                                           \
        _Pragma("unroll")                                                          \
        for (int j_ = 0; j_ < 2; j_++) {                                           \
            int idx_ = tid * 2 + j_;                                               \
            int r_ = idx_ >> 2, ch_ = idx_ & 3;                                    \
            unsigned da_ = (unsigned)__cvta_generic_to_shared(&As[s][r_][ch_*8]);  \
            unsigned db_ = (unsigned)__cvta_generic_to_shared(&Bs[s][r_][ch_*8]);  \
            asm volatile("cp.async.ca.shared.global [%0], [%1], 16;" ::            \
                "r"(da_), "l"(A + (size_t)(blockRow + r_) * K + (kb) + ch_*8));    \
            asm volatile("cp.async.ca.shared.global [%0], [%1], 16;" ::            \
                "r"(db_), "l"(B + (size_t)(blockCol + r_) * K + (kb) + ch_*8));    \
        }                                                                          \
        asm volatile("cp.async.commit_group;");                                    \
    } while (0)

    const int NT = K >> 5;   // BK=32
    LOAD_STAGE(0, 0);
    int st = 0;

    for (int t = 0; t < NT; t++) {
        if (t + 1 < NT) {
            LOAD_STAGE(st ^ 1, (t + 1) << 5);
            asm volatile("cp.async.wait_group 1;");
        } else {
            asm volatile("cp.async.wait_group 0;");
        }
        __syncthreads();

#pragma unroll
        for (int ks = 0; ks < 2; ks++) {
            const int k0 = ks << 4;
            uint32_t af[4][4], bf[4][2];
#pragma unroll
            for (int mt = 0; mt < 4; mt++) {
                const __half* p0 = &As[st][warpM + mt * 16 + gr][k0 + 2 * tg];
                const __half* p1 = p0 + 8 * 40;   // row +8
                af[mt][0] = ldh2(p0);
                af[mt][1] = ldh2(p1);
                af[mt][2] = ldh2(p0 + 8);
                af[mt][3] = ldh2(p1 + 8);
            }
#pragma unroll
            for (int nt = 0; nt < 4; nt++) {
                const __half* p = &Bs[st][warpN + nt * 8 + gr][k0 + 2 * tg];
                bf[nt][0] = ldh2(p);
                bf[nt][1] = ldh2(p + 8);
            }
#pragma unroll
            for (int mt = 0; mt < 4; mt++)
#pragma unroll
                for (int nt = 0; nt < 4; nt++)
                    mma_f16(c[mt][nt], af[mt][0], af[mt][1], af[mt][2], af[mt][3],
                            bf[nt][0], bf[nt][1]);
        }
        __syncthreads();
        st ^= 1;
    }
#undef LOAD_STAGE

    if (out_half) {
        __half* C = (__half*)Cv;
#pragma unroll
        for (int mt = 0; mt < 4; mt++) {
            int row = blockRow + warpM + mt * 16 + gr;
#pragma unroll
            for (int nt = 0; nt < 4; nt++) {
                int col = blockCol + warpN + nt * 8 + tg * 2;
                *(__half2*)(C + (size_t)row * N + col) =
                    __floats2half2_rn(c[mt][nt][0], c[mt][nt][1]);
                *(__half2*)(C + (size_t)(row + 8) * N + col) =
                    __floats2half2_rn(c[mt][nt][2], c[mt][nt][3]);
            }
        }
    } else {
        float* C = (float*)Cv;
#pragma unroll
        for (int mt = 0; mt < 4; mt++) {
            int row = blockRow + warpM + mt * 16 + gr;
#pragma unroll
            for (int nt = 0; nt < 4; nt++) {
                int col = blockCol + warpN + nt * 8 + tg * 2;
                *(float2*)(C + (size_t)row * N + col) =
                    make_float2(c[mt][nt][0], c[mt][nt][1]);
                *(float2*)(C + (size_t)(row + 8) * N + col) =
                    make_float2(c[mt][nt][2], c[mt][nt][3]);
            }
        }
    }
}

// ---------------- V transpose: g_v[M][512] -> g_vt[b][kvh][d][s] ----------
__global__ void vtrans_kernel(const __half* __restrict__ in, __half* __restrict__ out)
{
    __shared__ __half t[32][33];
    int b  = blockIdx.z;
    int c0 = blockIdx.y * 32;
    int s0 = blockIdx.x * 32;
    int x = threadIdx.x, y = threadIdx.y;   // 32 x 8
#pragma unroll
    for (int i = 0; i < 32; i += 8)
        t[y + i][x] = in[(size_t)(b * SEQ + s0 + y + i) * VCOLS + c0 + x];
    __syncthreads();
#pragma unroll
    for (int i = 0; i < 32; i += 8) {
        int c = c0 + y + i;
        // element (c = c0+y+i, s = s0+x) lives at t[x][y+i]  (FIX: was t[y+i][x])
        out[((size_t)(b * NKV + (c >> 7)) * VDIM + (c & 127)) * SEQ + s0 + x] = t[x][y + i];
    }
}

// ---------------- RoPE (fp16 in/out, fp32 math) ----------------
__global__ void rope_kernel(__half* __restrict__ x, int nheads, int total)
{
    int i = blockIdx.x * blockDim.x + threadIdx.x;
    if (i >= total) return;
    int d   = i & 31;
    int h   = (i >> 5) % nheads;
    int row = i / (32 * nheads);
    int s   = row & (SEQ - 1);

    double inv = exp2(-(double)d * (22.253496664211536 / 32.0));
    float ang  = (float)((double)s * inv);
    float sn, cs;
    sincosf(ang, &sn, &cs);

    __half* p = x + (size_t)row * nheads * QKD + h * QKD;
    float x1 = __half2float(p[d]), x2 = __half2float(p[d + 32]);
    p[d]      = __float2half_rn(x1 * cs - x2 * sn);
    p[d + 32] = __float2half_rn(x2 * cs + x1 * sn);
}

// ---------------- Flash attention v3: fp16 tensor-core ----------------
// 64x64 tiles, 256 threads = 8 warps.
// Scores: warp w -> rows [16*(w&3),+16), cols [32*(w>>2),+32), k16 x 12
// PV:     warp w -> rows [16*(w&3),+16), cols [64*(w>>2),+64), k16 x 4
#define HQS 200   // Qs/Ks row stride (halfs)
#define HPS 72    // Ps row stride (halfs)
#define HVS 72    // Vt row stride (halfs)
#define FSS 68    // Ss row stride (floats)
#define FLASH_SMEM ((64*HQS + 64*HQS + 128*HVS + 64*HPS) * 2 + (64*FSS + 64 + 64) * 4)

__global__ __launch_bounds__(256)
void flash3_kernel(const __half* __restrict__ Q, const __half* __restrict__ K,
                   const __half* __restrict__ Vt, __half* __restrict__ O)
{
    extern __shared__ char smraw[];
    __half* Qs  = (__half*)smraw;
    __half* Ks  = Qs + 64 * HQS;
    __half* Vs  = Ks + 64 * HQS;           // [128 d][HVS]
    __half* Ps  = Vs + 128 * HVS;
    float*  Ss  = (float*)(Ps + 64 * HPS);
    float*  scorr = Ss + 64 * FSS;
    float*  slinv = scorr + 64;

    const int qt = blockIdx.x;
    const int h  = blockIdx.y;
    const int b  = blockIdx.z;
    const int kh = h >> 3;

    const int tid  = threadIdx.x;
    const int wid  = tid >> 5;
    const int lane = tid & 31;
    const int gr   = lane >> 2;
    const int tg   = lane & 3;
    const int rs   = wid & 3;
    const int ch   = wid >> 2;

    const int r    = tid >> 2;
    const int quad = tid & 3;

    // ---- load Q tile (64 x 192 halfs) ----
    const size_t qbase = ((size_t)(b * SEQ + qt * 64)) * QCOLS + (size_t)h * QKD;
    for (int i = tid; i < 64 * 24; i += 256) {
        int row = i / 24, c8 = i % 24;
        *(uint4*)(Qs + row * HQS + c8 * 8) =
            *(const uint4*)(Q + qbase + (size_t)row * QCOLS + c8 * 8);
    }

    float m = -INFINITY, l = 0.f;
    float acc[8][4];
#pragma unroll
    for (int nt = 0; nt < 8; nt++)
#pragma unroll
        for (int i = 0; i < 4; i++) acc[nt][i] = 0.f;

    const int   qglob = qt * 64 + r;
    const float scale = 0.07216878364870323f;   // 1/sqrt(192)
    const int   nkt   = qt + 1;

    const __half* Qr0 = Qs + (16 * rs + gr) * HQS + 2 * tg;
    const __half* Kb  = Ks + (32 * ch + gr) * HQS + 2 * tg;
    const __half* Pr0 = Ps + (16 * rs + gr) * HPS + 2 * tg;
    const __half* Vb  = Vs + (64 * ch + gr) * HVS + 2 * tg;

    const size_t vtbase = ((size_t)(b * NKV + kh) * VDIM) * SEQ;

    for (int kt = 0; kt < nkt; kt++) {
        __syncthreads();   // S1: prior consumers of Ks/Vs/Ps done

        // ---- load K tile (64 x 192 halfs) ----
        const size_t kbase = ((size_t)(b * SEQ + kt * 64)) * KCOLS + (size_t)kh * QKD;
        for (int i = tid; i < 64 * 24; i += 256) {
            int row = i / 24, c8 = i % 24;
            *(uint4*)(Ks + row * HQS + c8 * 8) =
                *(const uint4*)(K + kbase + (size_t)row * KCOLS + c8 * 8);
        }
        // ---- load V^T tile (128 d x 64 s halfs) ----
        for (int i = tid; i < 128 * 8; i += 256) {
            int row = i >> 3, c8 = i & 7;
            *(uint4*)(Vs + row * HVS + c8 * 8) =
                *(const uint4*)(Vt + vtbase + (size_t)row * SEQ + kt * 64 + c8 * 8);
        }
        __syncthreads();   // S2: tiles ready

        // ---- scores: 16x32 per warp, 12 k16 tiles ----
        float cf[4][4];
#pragma unroll
        for (int nt = 0; nt < 4; nt++)
#pragma unroll
            for (int i = 0; i < 4; i++) cf[nt][i] = 0.f;

#pragma unroll 4
        for (int ktile = 0; ktile < 12; ktile++) {
            const int k0 = ktile * 16;
            uint32_t a0 = ldh2(Qr0 + k0);
            uint32_t a1 = ldh2(Qr0 + k0 + 8 * HQS);
            uint32_t a2 = ldh2(Qr0 + k0 + 8);
            uint32_t a3 = ldh2(Qr0 + k0 + 8 * HQS + 8);
#pragma unroll
            for (int nt = 0; nt < 4; nt++) {
                const __half* kp = Kb + nt * 8 * HQS + k0;
                mma_f16(cf[nt], a0, a1, a2, a3, ldh2(kp), ldh2(kp + 8));
            }
        }
        {
            float* s0 = Ss + (16 * rs + gr) * FSS + 32 * ch + 2 * tg;
#pragma unroll
            for (int nt = 0; nt < 4; nt++) {
                *(float2*)(s0 + nt * 8)           = make_float2(cf[nt][0], cf[nt][1]);
                *(float2*)(s0 + nt * 8 + 8 * FSS) = make_float2(cf[nt][2], cf[nt][3]);
            }
        }
        __syncthreads();   // S3: scores in smem

        // ---- online softmax (4 threads per row) ----
        {
            float* Srow = Ss + r * FSS;
            __half* Prow = Ps + r * HPS;
            float s[16];
            float tmax = -INFINITY;
#pragma unroll
            for (int j = 0; j < 16; j++) {
                int cg = kt * 64 + 4 * j + quad;
                float v = Srow[4 * j + quad] * scale;
                s[j] = (cg <= qglob) ? v : -INFINITY;
                tmax = fmaxf(tmax, s[j]);
            }
            tmax = fmaxf(tmax, __shfl_xor_sync(0xffffffffu, tmax, 1));
            tmax = fmaxf(tmax, __shfl_xor_sync(0xffffffffu, tmax, 2));
            float mnew = fmaxf(m, tmax);
            float corr = __expf(m - mnew);

            float psum = 0.f;
#pragma unroll
            for (int j = 0; j < 16; j++) {
                __half ph = __float2half_rn(__expf(s[j] - mnew));
                psum += __half2float(ph);
                Prow[4 * j + quad] = ph;
            }
            psum += __shfl_xor_sync(0xffffffffu, psum, 1);
            psum += __shfl_xor_sync(0xffffffffu, psum, 2);
            l = l * corr + psum;
            m = mnew;
            if (quad == 0) scorr[r] = corr;
        }
        __syncthreads();   // S4: P + corr ready

        // ---- PV: 16x64 per warp, 4 k16 tiles ----
        {
            float ca = scorr[16 * rs + gr];
            float cb = scorr[16 * rs + gr + 8];
#pragma unroll
            for (int nt = 0; nt < 8; nt++) {
                acc[nt][0] *= ca; acc[nt][1] *= ca;
                acc[nt][2] *= cb; acc[nt][3] *= cb;
            }
#pragma unroll
            for (int ktile = 0; ktile < 4; ktile++) {
                const int k0 = ktile * 16;
                uint32_t a0 = ldh2(Pr0 + k0);
                uint32_t a1 = ldh2(Pr0 + k0 + 8 * HPS);
                uint32_t a2 = ldh2(Pr0 + k0 + 8);
                uint32_t a3 = ldh2(Pr0 + k0 + 8 * HPS + 8);
#pragma unroll
                for (int nt = 0; nt < 8; nt++) {
                    const __half* vp = Vb + nt * 8 * HVS + k0;
                    mma_f16(acc[nt], a0, a1, a2, a3, ldh2(vp), ldh2(vp + 8));
                }
            }
        }
    }

    // ---- normalize, store fp16 ----
    if (quad == 0) slinv[r] = 1.0f / l;
    __syncthreads();

    const int row0 = 16 * rs + gr;
    const float inv0 = slinv[row0];
    const float inv1 = slinv[row0 + 8];
    __half* o0 = O + ((size_t)(b * SEQ + qt * 64 + row0)) * OCOLS
                   + h * VDIM + 64 * ch + 2 * tg;
#pragma unroll
    for (int nt = 0; nt < 8; nt++) {
        *(__half2*)(o0 + nt * 8) =
            __floats2half2_rn(acc[nt][0] * inv0, acc[nt][1] * inv0);
        *(__half2*)(o0 + nt * 8 + 8 * OCOLS) =
            __floats2half2_rn(acc[nt][2] * inv1, acc[nt][3] * inv1);
    }
}

// ---------------- launch ----------------
extern "C" void kernel_launch(void* const* d_in, const int* in_sizes, int n_in,
                              void* d_out, int out_size)
{
    const float* hs = (const float*)d_in[0];
    const float* wq = (const float*)d_in[3];
    const float* wk = (const float*)d_in[4];
    const float* wv = (const float*)d_in[5];
    const float* wo = (const float*)d_in[6];
    float* out = (float*)d_out;

    __half *qb, *kb, *vb, *vtb, *ab, *hsr, *wqr, *wkr, *wvr, *wor;
    cudaGetSymbolAddress((void**)&qb, g_q);
    cudaGetSymbolAddress((void**)&kb, g_k);
    cudaGetSymbolAddress((void**)&vb, g_v);
    cudaGetSymbolAddress((void**)&vtb, g_vt);
    cudaGetSymbolAddress((void**)&ab, g_att);
    cudaGetSymbolAddress((void**)&hsr, g_hs);
    cudaGetSymbolAddress((void**)&wqr, g_wq);
    cudaGetSymbolAddress((void**)&wkr, g_wk);
    cudaGetSymbolAddress((void**)&wvr, g_wv);
    cudaGetSymbolAddress((void**)&wor, g_wo);

    cudaFuncSetAttribute(flash3_kernel, cudaFuncAttributeMaxDynamicSharedMemorySize,
                         FLASH_SMEM);

    // fp32 -> fp16 conversion of GEMM operands
    {
        size_t n;
        n = (size_t)MROWS * HIDDEN / 4;
        tohalf_kernel<<<(unsigned)((n + 255) / 256), 256>>>(hs, hsr, n);
        n = (size_t)QCOLS * HIDDEN / 4;
        tohalf_kernel<<<(unsigned)((n + 255) / 256), 256>>>(wq, wqr, n);
        n = (size_t)KCOLS * HIDDEN / 4;
        tohalf_kernel<<<(unsigned)((n + 255) / 256), 256>>>(wk, wkr, n);
        n = (size_t)VCOLS * HIDDEN / 4;
        tohalf_kernel<<<(unsigned)((n + 255) / 256), 256>>>(wv, wvr, n);
        n = (size_t)HIDDEN * OCOLS / 4;
        tohalf_kernel<<<(unsigned)((n + 255) / 256), 256>>>(wo, wor, n);
    }

    dim3 blk(256);
    // projections (fp16 out)
    gemm_h<<<dim3(QCOLS / 128, MROWS / 128), blk>>>(hsr, wqr, qb, MROWS, QCOLS, HIDDEN, 1);
    gemm_h<<<dim3(KCOLS / 128, MROWS / 128), blk>>>(hsr, wkr, kb, MROWS, KCOLS, HIDDEN, 1);
    gemm_h<<<dim3(VCOLS / 128, MROWS / 128), blk>>>(hsr, wvr, vb, MROWS, VCOLS, HIDDEN, 1);
    // V transpose to [b][kvh][d][s]
    vtrans_kernel<<<dim3(SEQ / 32, VCOLS / 32, BATCH), dim3(32, 8)>>>(vb, vtb);
    // rope
    {
        int tq = MROWS * NH * 32;
        int tk = MROWS * NKV * 32;
        rope_kernel<<<(tq + 255) / 256, 256>>>(qb, NH, tq);
        rope_kernel<<<(tk + 255) / 256, 256>>>(kb, NKV, tk);
    }
    // attention (fp16 tensor core)
    flash3_kernel<<<dim3(SEQ / 64, NH, BATCH), 256, FLASH_SMEM>>>(qb, kb, vtb, ab);
    // output projection (fp32 out)
    gemm_h<<<dim3(OCOLS / 128, MROWS / 128), blk>>>(ab, wor, out, MROWS, OCOLS, HIDDEN, 0);
}

// round 7
// speedup vs baseline: 10.3476x; 1.3258x over previous
#include <cuda_runtime.h>
#include <cuda_fp16.h>
#include <math.h>
#include <stdint.h>

// ---------------- problem constants ----------------
#define BATCH   2
#define SEQ     2048
#define HIDDEN  4096
#define NH      32
#define NKV     4
#define QKD     192
#define VDIM    128
#define MROWS   (BATCH*SEQ)          // 4096
#define QCOLS   (NH*QKD)             // 6144
#define KCOLS   (NKV*QKD)            // 768
#define VCOLS   (NKV*VDIM)           // 512
#define OCOLS   (NH*VDIM)            // 4096

// ---------------- scratch (device globals: allocation-free) ----------------
__device__ __half g_q  [(size_t)MROWS * QCOLS];
__device__ __half g_k  [(size_t)MROWS * KCOLS];
__device__ __half g_v  [(size_t)MROWS * VCOLS];
__device__ __half g_vt [(size_t)BATCH * NKV * VDIM * SEQ];
__device__ __half g_att[(size_t)MROWS * OCOLS];
__device__ __half g_hs [(size_t)MROWS * HIDDEN];
__device__ __half g_wq [(size_t)QCOLS * HIDDEN];
__device__ __half g_wk [(size_t)KCOLS * HIDDEN];
__device__ __half g_wv [(size_t)VCOLS * HIDDEN];
__device__ __half g_wo [(size_t)HIDDEN * OCOLS];
__device__ float2 g_rope[(size_t)SEQ * 32];   // (cos, sin) per (s, d)

// ---------------- helpers ----------------
__device__ __forceinline__ void mma_f16(float c[4], uint32_t a0, uint32_t a1,
                                        uint32_t a2, uint32_t a3,
                                        uint32_t b0, uint32_t b1)
{
    asm volatile(
        "mma.sync.aligned.m16n8k16.row.col.f32.f16.f16.f32 "
        "{%0,%1,%2,%3}, {%4,%5,%6,%7}, {%8,%9}, {%0,%1,%2,%3};"
        : "+f"(c[0]), "+f"(c[1]), "+f"(c[2]), "+f"(c[3])
        : "r"(a0), "r"(a1), "r"(a2), "r"(a3), "r"(b0), "r"(b1));
}
__device__ __forceinline__ void ldsm4(uint32_t r[4], const __half* p) {
    uint32_t a = (uint32_t)__cvta_generic_to_shared(p);
    asm volatile("ldmatrix.sync.aligned.m8n8.x4.shared.b16 {%0,%1,%2,%3}, [%4];"
                 : "=r"(r[0]), "=r"(r[1]), "=r"(r[2]), "=r"(r[3]) : "r"(a));
}

// ---------------- fp32 -> fp16 conversion (8 elems/thread, 16B store) ----
__global__ void tohalf_kernel(const float4* __restrict__ in, uint4* __restrict__ out,
                              size_t n8)
{
    size_t i = (size_t)blockIdx.x * blockDim.x + threadIdx.x;
    if (i >= n8) return;
    float4 v0 = in[2 * i], v1 = in[2 * i + 1];
    __half2 h0 = __floats2half2_rn(v0.x, v0.y);
    __half2 h1 = __floats2half2_rn(v0.z, v0.w);
    __half2 h2 = __floats2half2_rn(v1.x, v1.y);
    __half2 h3 = __floats2half2_rn(v1.z, v1.w);
    uint4 o;
    o.x = *reinterpret_cast<uint32_t*>(&h0);
    o.y = *reinterpret_cast<uint32_t*>(&h1);
    o.z = *reinterpret_cast<uint32_t*>(&h2);
    o.w = *reinterpret_cast<uint32_t*>(&h3);
    out[i] = o;
}

// ---------------- fp16 tensor-core GEMM, 3-stage, ldmatrix ----------------
// C[M,N] = A[M,K] * B[N,K]^T. BM=BN=128, BK=32, 256 thr = 8 warps (2x4).
#define GSTG 3
#define GSTAGE_H 5120                      // 128*40 halfs per stage per array
#define GEMM_SMEM (GSTG * 2 * GSTAGE_H * 2)  // 61440 bytes

__global__ __launch_bounds__(256)
void gemm_h(const __half* __restrict__ A, const __half* __restrict__ B,
            void* __restrict__ Cv, int M, int N, int K, int out_half)
{
    extern __shared__ __half smh[];
    __half* As0 = smh;
    __half* Bs0 = smh + GSTG * GSTAGE_H;

    const int tid  = threadIdx.x;
    const int lane = tid & 31;
    const int wid  = tid >> 5;
    const int warpM = (wid >> 2) << 6;
    const int warpN = (wid & 3) << 5;
    const int gr = lane >> 2;
    const int tg = lane & 3;
    const int l8 = lane & 7;
    const int qd = lane >> 3;

    const int blockRow = blockIdx.y * 128;
    const int blockCol = blockIdx.x * 128;

    float c[4][4][4];
#pragma unroll
    for (int mt = 0; mt < 4; mt++)
#pragma unroll
        for (int nt = 0; nt < 4; nt++)
#pragma unroll
            for (int i = 0; i < 4; i++) c[mt][nt][i] = 0.f;

#define LOAD_STAGE(sp, kb)                                                         \
    do {                                                                           \
        __half* aS = As0 + (sp) * GSTAGE_H;                                        \
        __half* bS = Bs0 + (sp) * GSTAGE_H;                                        \
        _Pragma("unroll")                                                          \
        for (int j_ = 0; j_ < 2; j_++) {                                           \
            int idx_ = tid * 2 + j_;                                               \
            int r_ = idx_ >> 2, ch_ = idx_ & 3;                                    \
            unsigned da_ = (unsigned)__cvta_generic_to_shared(aS + r_*40 + ch_*8); \
            unsigned db_ = (unsigned)__cvta_generic_to_shared(bS + r_*40 + ch_*8); \
            asm volatile("cp.async.ca.shared.global [%0], [%1], 16;" ::            \
                "r"(da_), "l"(A + (size_t)(blockRow + r_) * K + (kb) + ch_*8));    \
            asm volatile("cp.async.ca.shared.global [%0], [%1], 16;" ::            \
                "r"(db_), "l"(B + (size_t)(blockCol + r_) * K + (kb) + ch_*8));    \
        }                                                                          \
    } while (0)

    const int NT = K >> 5;   // BK=32
    LOAD_STAGE(0, 0);
    asm volatile("cp.async.commit_group;");
    LOAD_STAGE(1, 32);
    asm volatile("cp.async.commit_group;");

    // fragment load offsets
    const int aoff = ((qd & 1) * 8 + l8) * 40 + (qd >> 1) * 8;
    const int boff = ((qd >> 1) * 8 + l8) * 40 + (qd & 1) * 8;

    for (int t = 0; t < NT; t++) {
        asm volatile("cp.async.wait_group 1;");
        __syncthreads();

        int tp = t + 2;
        if (tp < NT) LOAD_STAGE(tp % GSTG, tp << 5);
        asm volatile("cp.async.commit_group;");

        const __half* aS = As0 + (t % GSTG) * GSTAGE_H;
        const __half* bS = Bs0 + (t % GSTG) * GSTAGE_H;

#pragma unroll
        for (int ks = 0; ks < 2; ks++) {
            const int k0 = ks << 4;
            uint32_t af[4][4], bf[2][4];
#pragma unroll
            for (int mt = 0; mt < 4; mt++)
                ldsm4(af[mt], aS + (warpM + mt * 16) * 40 + k0 + aoff);
#pragma unroll
            for (int np = 0; np < 2; np++)
                ldsm4(bf[np], bS + (warpN + np * 16) * 40 + k0 + boff);
#pragma unroll
            for (int mt = 0; mt < 4; mt++)
#pragma unroll
                for (int nt = 0; nt < 4; nt++)
                    mma_f16(c[mt][nt], af[mt][0], af[mt][1], af[mt][2], af[mt][3],
                            bf[nt >> 1][(nt & 1) * 2], bf[nt >> 1][(nt & 1) * 2 + 1]);
        }
    }
#undef LOAD_STAGE

    if (out_half) {
        __half* C = (__half*)Cv;
#pragma unroll
        for (int mt = 0; mt < 4; mt++) {
            int row = blockRow + warpM + mt * 16 + gr;
#pragma unroll
            for (int nt = 0; nt < 4; nt++) {
                int col = blockCol + warpN + nt * 8 + tg * 2;
                *(__half2*)(C + (size_t)row * N + col) =
                    __floats2half2_rn(c[mt][nt][0], c[mt][nt][1]);
                *(__half2*)(C + (size_t)(row + 8) * N + col) =
                    __floats2half2_rn(c[mt][nt][2], c[mt][nt][3]);
            }
        }
    } else {
        float* C = (float*)Cv;
#pragma unroll
        for (int mt = 0; mt < 4; mt++) {
            int row = blockRow + warpM + mt * 16 + gr;
#pragma unroll
            for (int nt = 0; nt < 4; nt++) {
                int col = blockCol + warpN + nt * 8 + tg * 2;
                *(float2*)(C + (size_t)row * N + col) =
                    make_float2(c[mt][nt][0], c[mt][nt][1]);
                *(float2*)(C + (size_t)(row + 8) * N + col) =
                    make_float2(c[mt][nt][2], c[mt][nt][3]);
            }
        }
    }
}

// ---------------- V transpose: g_v[M][512] -> g_vt[b][kvh][d][s] ----------
__global__ void vtrans_kernel(const __half* __restrict__ in, __half* __restrict__ out)
{
    __shared__ __half t[32][33];
    int b  = blockIdx.z;
    int c0 = blockIdx.y * 32;
    int s0 = blockIdx.x * 32;
    int x = threadIdx.x, y = threadIdx.y;   // 32 x 8
#pragma unroll
    for (int i = 0; i < 32; i += 8)
        t[y + i][x] = in[(size_t)(b * SEQ + s0 + y + i) * VCOLS + c0 + x];
    __syncthreads();
#pragma unroll
    for (int i = 0; i < 32; i += 8) {
        int c = c0 + y + i;
        out[((size_t)(b * NKV + (c >> 7)) * VDIM + (c & 127)) * SEQ + s0 + x] = t[x][y + i];
    }
}

// ---------------- RoPE: table + vectorized apply ----------------
__global__ void rope_table_kernel()
{
    int i = blockIdx.x * blockDim.x + threadIdx.x;   // 65536
    int d = i & 31, s = i >> 5;
    float inv = exp2f(-(float)d * (22.253496664211536f / 32.0f));
    float ang = (float)s * inv;
    float sn, cs;
    sincosf(ang, &sn, &cs);
    g_rope[i] = make_float2(cs, sn);
}

// one thread per (row, head): rotates 64 halfs with 16B accesses
__global__ void rope_apply_kernel(__half* __restrict__ x, int nheads, int total)
{
    int idx = blockIdx.x * blockDim.x + threadIdx.x;
    if (idx >= total) return;
    int h   = idx % nheads;
    int row = idx / nheads;
    int s   = row & (SEQ - 1);

    uint4* p4 = (uint4*)(x + (size_t)row * nheads * QKD + h * QKD);
    const float2* tab = g_rope + s * 32;

    uint4 buf[8];
#pragma unroll
    for (int j = 0; j < 8; j++) buf[j] = p4[j];
    __half2* hp = (__half2*)buf;    // hp[0..15] = d 0..31 (x1), hp[16..31] = d 32..63 (x2)
#pragma unroll
    for (int j = 0; j < 16; j++) {
        float2 a = __half22float2(hp[j]);
        float2 b = __half22float2(hp[j + 16]);
        float2 t0 = tab[2 * j], t1 = tab[2 * j + 1];
        hp[j]      = __floats2half2_rn(a.x * t0.x - b.x * t0.y,
                                       a.y * t1.x - b.y * t1.y);
        hp[j + 16] = __floats2half2_rn(b.x * t0.x + a.x * t0.y,
                                       b.y * t1.x + a.y * t1.y);
    }
#pragma unroll
    for (int j = 0; j < 8; j++) p4[j] = buf[j];
}

// ---------------- Flash attention: fp16 tensor-core + ldmatrix ------------
#define HQS 200   // Qs/Ks row stride (halfs)
#define HPS 72    // Ps row stride (halfs)
#define HVS 72    // Vt row stride (halfs)
#define FSS 68    // Ss row stride (floats)
#define FLASH_SMEM ((64*HQS + 64*HQS + 128*HVS + 64*HPS) * 2 + (64*FSS + 64 + 64) * 4)

__global__ __launch_bounds__(256)
void flash3_kernel(const __half* __restrict__ Q, const __half* __restrict__ K,
                   const __half* __restrict__ Vt, __half* __restrict__ O)
{
    extern __shared__ char smraw[];
    __half* Qs  = (__half*)smraw;
    __half* Ks  = Qs + 64 * HQS;
    __half* Vs  = Ks + 64 * HQS;           // [128 d][HVS]
    __half* Ps  = Vs + 128 * HVS;
    float*  Ss  = (float*)(Ps + 64 * HPS);
    float*  scorr = Ss + 64 * FSS;
    float*  slinv = scorr + 64;

    const int qt = blockIdx.x;
    const int h  = blockIdx.y;
    const int b  = blockIdx.z;
    const int kh = h >> 3;

    const int tid  = threadIdx.x;
    const int wid  = tid >> 5;
    const int lane = tid & 31;
    const int gr   = lane >> 2;
    const int tg   = lane & 3;
    const int l8   = lane & 7;
    const int qd   = lane >> 3;
    const int rs   = wid & 3;
    const int ch   = wid >> 2;

    const int r    = tid >> 2;
    const int quad = tid & 3;

    // ---- load Q tile (64 x 192 halfs) ----
    const size_t qbase = ((size_t)(b * SEQ + qt * 64)) * QCOLS + (size_t)h * QKD;
    for (int i = tid; i < 64 * 24; i += 256) {
        int row = i / 24, c8 = i % 24;
        *(uint4*)(Qs + row * HQS + c8 * 8) =
            *(const uint4*)(Q + qbase + (size_t)row * QCOLS + c8 * 8);
    }

    float m = -INFINITY, l = 0.f;
    float acc[8][4];
#pragma unroll
    for (int nt = 0; nt < 8; nt++)
#pragma unroll
        for (int i = 0; i < 4; i++) acc[nt][i] = 0.f;

    const int   qglob = qt * 64 + r;
    const float scale = 0.07216878364870323f;   // 1/sqrt(192)
    const int   nkt   = qt + 1;

    // ldmatrix base pointers (A-type for Q/P, B-type for K/V)
    const __half* Qld = Qs + (16 * rs + (qd & 1) * 8 + l8) * HQS + (qd >> 1) * 8;
    const __half* Kld = Ks + (32 * ch + (qd >> 1) * 8 + l8) * HQS + (qd & 1) * 8;
    const __half* Pld = Ps + (16 * rs + (qd & 1) * 8 + l8) * HPS + (qd >> 1) * 8;
    const __half* Vld = Vs + (64 * ch + (qd >> 1) * 8 + l8) * HVS + (qd & 1) * 8;

    const size_t vtbase = ((size_t)(b * NKV + kh) * VDIM) * SEQ;

    for (int kt = 0; kt < nkt; kt++) {
        __syncthreads();   // S1: prior consumers of Ks/Vs/Ps done

        const size_t kbase = ((size_t)(b * SEQ + kt * 64)) * KCOLS + (size_t)kh * QKD;
        for (int i = tid; i < 64 * 24; i += 256) {
            int row = i / 24, c8 = i % 24;
            *(uint4*)(Ks + row * HQS + c8 * 8) =
                *(const uint4*)(K + kbase + (size_t)row * KCOLS + c8 * 8);
        }
        for (int i = tid; i < 128 * 8; i += 256) {
            int row = i >> 3, c8 = i & 7;
            *(uint4*)(Vs + row * HVS + c8 * 8) =
                *(const uint4*)(Vt + vtbase + (size_t)row * SEQ + kt * 64 + c8 * 8);
        }
        __syncthreads();   // S2: tiles ready

        // ---- scores: 16x32 per warp, 12 k16 tiles, ldmatrix frags ----
        float cf[4][4];
#pragma unroll
        for (int nt = 0; nt < 4; nt++)
#pragma unroll
            for (int i = 0; i < 4; i++) cf[nt][i] = 0.f;

#pragma unroll 4
        for (int ktile = 0; ktile < 12; ktile++) {
            const int k0 = ktile * 16;
            uint32_t af[4], bf0[4], bf1[4];
            ldsm4(af, Qld + k0);
            ldsm4(bf0, Kld + k0);
            ldsm4(bf1, Kld + 16 * HQS + k0);
            mma_f16(cf[0], af[0], af[1], af[2], af[3], bf0[0], bf0[1]);
            mma_f16(cf[1], af[0], af[1], af[2], af[3], bf0[2], bf0[3]);
            mma_f16(cf[2], af[0], af[1], af[2], af[3], bf1[0], bf1[1]);
            mma_f16(cf[3], af[0], af[1], af[2], af[3], bf1[2], bf1[3]);
        }
        {
            float* s0 = Ss + (16 * rs + gr) * FSS + 32 * ch + 2 * tg;
#pragma unroll
            for (int nt = 0; nt < 4; nt++) {
                *(float2*)(s0 + nt * 8)           = make_float2(cf[nt][0], cf[nt][1]);
                *(float2*)(s0 + nt * 8 + 8 * FSS) = make_float2(cf[nt][2], cf[nt][3]);
            }
        }
        __syncthreads();   // S3: scores in smem

        // ---- online softmax (4 threads per row) ----
        {
            float* Srow = Ss + r * FSS;
            __half* Prow = Ps + r * HPS;
            float s[16];
            float tmax = -INFINITY;
#pragma unroll
            for (int j = 0; j < 16; j++) {
                int cg = kt * 64 + 4 * j + quad;
                float v = Srow[4 * j + quad] * scale;
                s[j] = (cg <= qglob) ? v : -INFINITY;
                tmax = fmaxf(tmax, s[j]);
            }
            tmax = fmaxf(tmax, __shfl_xor_sync(0xffffffffu, tmax, 1));
            tmax = fmaxf(tmax, __shfl_xor_sync(0xffffffffu, tmax, 2));
            float mnew = fmaxf(m, tmax);
            float corr = __expf(m - mnew);

            float psum = 0.f;
#pragma unroll
            for (int j = 0; j < 16; j++) {
                __half ph = __float2half_rn(__expf(s[j] - mnew));
                psum += __half2float(ph);
                Prow[4 * j + quad] = ph;
            }
            psum += __shfl_xor_sync(0xffffffffu, psum, 1);
            psum += __shfl_xor_sync(0xffffffffu, psum, 2);
            l = l * corr + psum;
            m = mnew;
            if (quad == 0) scorr[r] = corr;
        }
        __syncthreads();   // S4: P + corr ready

        // ---- PV: 16x64 per warp, 4 k16 tiles, ldmatrix frags ----
        {
            float ca = scorr[16 * rs + gr];
            float cb = scorr[16 * rs + gr + 8];
#pragma unroll
            for (int nt = 0; nt < 8; nt++) {
                acc[nt][0] *= ca; acc[nt][1] *= ca;
                acc[nt][2] *= cb; acc[nt][3] *= cb;
            }
#pragma unroll
            for (int ktile = 0; ktile < 4; ktile++) {
                const int k0 = ktile * 16;
                uint32_t af[4];
                ldsm4(af, Pld + k0);
#pragma unroll
                for (int np = 0; np < 4; np++) {
                    uint32_t bf[4];
                    ldsm4(bf, Vld + np * 16 * HVS + k0);
                    mma_f16(acc[2 * np],     af[0], af[1], af[2], af[3], bf[0], bf[1]);
                    mma_f16(acc[2 * np + 1], af[0], af[1], af[2], af[3], bf[2], bf[3]);
                }
            }
        }
    }

    // ---- normalize, store fp16 ----
    if (quad == 0) slinv[r] = 1.0f / l;
    __syncthreads();

    const int row0 = 16 * rs + gr;
    const float inv0 = slinv[row0];
    const float inv1 = slinv[row0 + 8];
    __half* o0 = O + ((size_t)(b * SEQ + qt * 64 + row0)) * OCOLS
                   + h * VDIM + 64 * ch + 2 * tg;
#pragma unroll
    for (int nt = 0; nt < 8; nt++) {
        *(__half2*)(o0 + nt * 8) =
            __floats2half2_rn(acc[nt][0] * inv0, acc[nt][1] * inv0);
        *(__half2*)(o0 + nt * 8 + 8 * OCOLS) =
            __floats2half2_rn(acc[nt][2] * inv1, acc[nt][3] * inv1);
    }
}

// ---------------- launch ----------------
extern "C" void kernel_launch(void* const* d_in, const int* in_sizes, int n_in,
                              void* d_out, int out_size)
{
    const float* hs = (const float*)d_in[0];
    const float* wq = (const float*)d_in[3];
    const float* wk = (const float*)d_in[4];
    const float* wv = (const float*)d_in[5];
    const float* wo = (const float*)d_in[6];
    float* out = (float*)d_out;

    __half *qb, *kb, *vb, *vtb, *ab, *hsr, *wqr, *wkr, *wvr, *wor;
    cudaGetSymbolAddress((void**)&qb, g_q);
    cudaGetSymbolAddress((void**)&kb, g_k);
    cudaGetSymbolAddress((void**)&vb, g_v);
    cudaGetSymbolAddress((void**)&vtb, g_vt);
    cudaGetSymbolAddress((void**)&ab, g_att);
    cudaGetSymbolAddress((void**)&hsr, g_hs);
    cudaGetSymbolAddress((void**)&wqr, g_wq);
    cudaGetSymbolAddress((void**)&wkr, g_wk);
    cudaGetSymbolAddress((void**)&wvr, g_wv);
    cudaGetSymbolAddress((void**)&wor, g_wo);

    cudaFuncSetAttribute(flash3_kernel, cudaFuncAttributeMaxDynamicSharedMemorySize,
                         FLASH_SMEM);
    cudaFuncSetAttribute(gemm_h, cudaFuncAttributeMaxDynamicSharedMemorySize,
                         GEMM_SMEM);

    // rope table (cheap, deterministic)
    rope_table_kernel<<<SEQ * 32 / 256, 256>>>();

    // fp32 -> fp16 conversion of GEMM operands
    {
        size_t n;
        n = (size_t)MROWS * HIDDEN / 8;
        tohalf_kernel<<<(unsigned)((n + 255) / 256), 256>>>((const float4*)hs, (uint4*)hsr, n);
        n = (size_t)QCOLS * HIDDEN / 8;
        tohalf_kernel<<<(unsigned)((n + 255) / 256), 256>>>((const float4*)wq, (uint4*)wqr, n);
        n = (size_t)KCOLS * HIDDEN / 8;
        tohalf_kernel<<<(unsigned)((n + 255) / 256), 256>>>((const float4*)wk, (uint4*)wkr, n);
        n = (size_t)VCOLS * HIDDEN / 8;
        tohalf_kernel<<<(unsigned)((n + 255) / 256), 256>>>((const float4*)wv, (uint4*)wvr, n);
        n = (size_t)HIDDEN * OCOLS / 8;
        tohalf_kernel<<<(unsigned)((n + 255) / 256), 256>>>((const float4*)wo, (uint4*)wor, n);
    }

    dim3 blk(256);
    // projections (fp16 out)
    gemm_h<<<dim3(QCOLS / 128, MROWS / 128), blk, GEMM_SMEM>>>(hsr, wqr, qb, MROWS, QCOLS, HIDDEN, 1);
    gemm_h<<<dim3(KCOLS / 128, MROWS / 128), blk, GEMM_SMEM>>>(hsr, wkr, kb, MROWS, KCOLS, HIDDEN, 1);
    gemm_h<<<dim3(VCOLS / 128, MROWS / 128), blk, GEMM_SMEM>>>(hsr, wvr, vb, MROWS, VCOLS, HIDDEN, 1);
    // V transpose to [b][kvh][d][s]
    vtrans_kernel<<<dim3(SEQ / 32, VCOLS / 32, BATCH), dim3(32, 8)>>>(vb, vtb);
    // rope (table-driven)
    rope_apply_kernel<<<(MROWS * NH + 255) / 256, 256>>>(qb, NH, MROWS * NH);
    rope_apply_kernel<<<(MROWS * NKV + 255) / 256, 256>>>(kb, NKV, MROWS * NKV);
    // attention
    flash3_kernel<<<dim3(SEQ / 64, NH, BATCH), 256, FLASH_SMEM>>>(qb, kb, vtb, ab);
    // output projection (fp32 out)
    gemm_h<<<dim3(OCOLS / 128, MROWS / 128), blk, GEMM_SMEM>>>(ab, wor, out, MROWS, OCOLS, HIDDEN, 0);
}